// round 15
// baseline (speedup 1.0000x reference)
#include <cuda_runtime.h>
#include <cuda_fp16.h>
#include <cstdint>

// Fused SConv via warp-level fp16 mma.sync GEMM.
// out[m=128, n] = sum_k W[m,k] * z[k,n], K=576, 64 pixels per CTA.
// R15: 64n x 32m warp tiles (8 warps = 2 ksp x 4 mq) -> B fragments loaded
//      exactly once per CTA (-75% B LDG wavefronts). Transform as R14.

#define NTHREADS 256
#define ZSTRIDE 1168         // 576*2 + 16 pad (ldmatrix conflict-free)
#define XR 72                // floats per x row (cols w0-4 .. w0+67)
#define XC 217               // floats per channel (3*72 + 1 pad)

#define OFF_Z   0            // 64 x 1168 = 74752
#define OFF_XS  74752        // 32*217*4 = 27776
#define OFF_OB  0            // epilogue [64][129] f32 (overlaps Z, after GEMM)
#define OFF_CF  102528       // cfT: 9 j x 8 q floats
#define SMEM_BYTES 102912

// W fragment buffer: [mq 4][ch 9][ks 4][p 2][lane 32] x uint4 (4 regs)
__device__ __align__(16) uint32_t g_Wfrag[4 * 9 * 4 * 2 * 32 * 4];

__device__ __forceinline__ uint32_t smem_u32(const void* p) {
    uint32_t a;
    asm("{ .reg .u64 t; cvta.to.shared.u64 t, %1; cvt.u32.u64 %0, t; }" : "=r"(a) : "l"(p));
    return a;
}
__device__ __forceinline__ void ldm_x4(uint32_t* r, uint32_t addr) {
    asm volatile("ldmatrix.sync.aligned.m8n8.x4.shared.b16 {%0,%1,%2,%3}, [%4];"
                 : "=r"(r[0]), "=r"(r[1]), "=r"(r[2]), "=r"(r[3]) : "r"(addr));
}
__device__ __forceinline__ void mma16816(float* d, const uint32_t* a,
                                         uint32_t b0, uint32_t b1) {
    asm volatile("mma.sync.aligned.m16n8k16.row.col.f32.f16.f16.f32 "
                 "{%0,%1,%2,%3}, {%4,%5,%6,%7}, {%8,%9}, {%0,%1,%2,%3};"
                 : "+f"(d[0]), "+f"(d[1]), "+f"(d[2]), "+f"(d[3])
                 : "r"(a[0]), "r"(a[1]), "r"(a[2]), "r"(a[3]), "r"(b0), "r"(b1));
}

// ---------------- W pre-pack into fragment order ----------------
__global__ void prepack_w(const float* __restrict__ wg) {
    int idx = blockIdx.x * blockDim.x + threadIdx.x;   // 36864
    if (idx >= 4 * 9 * 4 * 2 * 32 * 4) return;
    int q = idx & 3;  int r = idx >> 2;
    int l = r & 31;   r >>= 5;
    int p = r & 1;    r >>= 1;
    int ks = r & 3;   r >>= 2;
    int ch = r % 9;
    int mq = r / 9;
    int m = mq * 32 + p * 16 + ((q >> 1) << 3) + (l >> 2);
    int k = ch * 64 + ks * 16 + ((q & 1) << 3) + ((l & 3) << 1);
    __half h0 = __float2half_rn(wg[m * 576 + k]);
    __half h1 = __float2half_rn(wg[m * 576 + k + 1]);
    g_Wfrag[idx] = (uint32_t)__half_as_ushort(h0) |
                   ((uint32_t)__half_as_ushort(h1) << 16);
}

// transform one pixel of one channel from register-held u[18] (3 rows x 6 cols)
__device__ __forceinline__ void transform_px(const float* __restrict__ u, int px,
                                             const float4* __restrict__ cfT4,
                                             float* __restrict__ out9) {
    float y0 = 0, y1 = 0, y2 = 0, y3 = 0, y4 = 0, y5 = 0, y6 = 0, y7 = 0;
#pragma unroll
    for (int j = 0; j < 9; ++j) {
        int r = j / 3, c2 = j % 3;
        float vj = u[r * 6 + px + c2];
        float4 cA = cfT4[j * 2];
        float4 cB = cfT4[j * 2 + 1];
        y0 = fmaf(cA.x, vj, y0); y1 = fmaf(cA.y, vj, y1);
        y2 = fmaf(cA.z, vj, y2); y3 = fmaf(cA.w, vj, y3);
        y4 = fmaf(cB.x, vj, y4); y5 = fmaf(cB.y, vj, y5);
        y6 = fmaf(cB.z, vj, y6); y7 = fmaf(cB.w, vj, y7);
    }
    float yv[8] = { y0, y1, y2, y3, y4, y5, y6, y7 };
#define CS(a, bb) { float _l = fminf(yv[a], yv[bb]); float _h = fmaxf(yv[a], yv[bb]); yv[a] = _l; yv[bb] = _h; }
    CS(0,1) CS(2,3) CS(4,5) CS(6,7)
    CS(0,2) CS(1,3) CS(4,6) CS(5,7)
    CS(1,2) CS(5,6)
    CS(0,4) CS(1,5) CS(2,6) CS(3,7)
    CS(2,4) CS(3,5)
    CS(1,2) CS(3,4) CS(5,6)
#undef CS
    out9[0] = yv[0]; out9[1] = yv[1]; out9[2] = yv[2]; out9[3] = yv[3];
    out9[4] = u[6 + px + 1];   // center v4
    out9[5] = yv[4]; out9[6] = yv[5]; out9[7] = yv[6]; out9[8] = yv[7];
}

// ---------------- main fused kernel ----------------
__global__ __launch_bounds__(NTHREADS, 2)
void sconv_mma_kernel(const float* __restrict__ xg,
                      const float* __restrict__ coefg,
                      const float* __restrict__ biasg,
                      float* __restrict__ outg) {
    extern __shared__ __align__(1024) unsigned char smem[];
    const uint32_t sb = smem_u32(smem);
    const int t   = threadIdx.x;
    const int wid = t >> 5;
    const int lid = t & 31;
    const int b   = blockIdx.z;
    const int h   = blockIdx.y;
    const int w0  = blockIdx.x * 64;

    float* xs = reinterpret_cast<float*>(smem + OFF_XS);
    float* cfT = reinterpret_cast<float*>(smem + OFF_CF);
    const float4* cfT4 = reinterpret_cast<const float4*>(smem + OFF_CF);

    if (t < 72) {
        int j = t >> 3, q = t & 7;
        int ri = q + (q >= 4 ? 1 : 0);
        cfT[j * 8 + q] = coefg[ri * 9 + j];
    }

    // warp roles: ksp = wid>>2 (K half), mq = wid&3 (32-m quarter); n = all 64 px
    const int ksp = wid >> 2;
    const int mq  = wid & 3;

    // A (z) ldmatrix x4 addressing: 16n x 16k tiles (nb adds nb*16*ZSTRIDE)
    const int rA   = lid & 7;
    const int matA = lid >> 3;
    const uint32_t aBase = sb + OFF_Z +
        (uint32_t)(rA + ((matA & 1) << 3)) * ZSTRIDE + (((matA >> 1) << 3) << 1);

    const uint4* wf0 = reinterpret_cast<const uint4*>(g_Wfrag) +
                       (uint32_t)mq * (9 * 4 * 2 * 32) + lid;

    // transform lane roles: cp = ch-pair, q4 = pixel quad
    const int cp  = t & 15;
    const int q4  = t >> 4;           // 0..15
    const int nn0 = q4 * 4;

    // ---- build full z (K=576) in two 32-channel phases
    for (int cc = 0; cc < 2; ++cc) {
        __syncthreads();   // xs region free

        // stage x: ch = t>>3, lane8 = t&7; 18 vec x 3 rows per channel
        {
            const float* xb = xg + (((long long)b * 64 + cc * 32) << 14);
            int c    = t >> 3;
            int l8   = t & 7;
            const float* xc = xb + (c << 14);
            float* xd = xs + c * XC;
#pragma unroll
            for (int j0 = 0; j0 < 7; ++j0) {
                int j = l8 + j0 * 8;
                if (j < 54) {
                    int r = j / 18, v = j % 18;
                    int gr = h + r - 1;
                    int gcb = w0 - 4 + 4 * v;
                    float4 val = make_float4(0.f, 0.f, 0.f, 0.f);
                    if ((unsigned)gr < 128u && gcb >= 0 && gcb + 3 < 128)
                        val = *reinterpret_cast<const float4*>(xc + (gr << 7) + gcb);
                    float* d = xd + r * XR + 4 * v;
                    d[0] = val.x; d[1] = val.y; d[2] = val.z; d[3] = val.w;
                }
            }
        }
        __syncthreads();

        // transform: thread = (ch pair 2cp,2cp+1) x (pixel quad nn0..nn0+3)
        {
            const float* xr0 = xs + (2 * cp) * XC;
            const float* xr1 = xr0 + XC;
            float u0[18], u1[18];
#pragma unroll
            for (int r = 0; r < 3; ++r)
#pragma unroll
                for (int c2 = 0; c2 < 6; ++c2) {
                    u0[r * 6 + c2] = xr0[r * XR + nn0 + 3 + c2];
                    u1[r * 6 + c2] = xr1[r * XR + nn0 + 3 + c2];
                }
            const uint32_t zcol = (uint32_t)(cc * 32 + 2 * cp) * 18;
#pragma unroll
            for (int px = 0; px < 4; ++px) {
                float s18[18];
                transform_px(u0, px, cfT4, s18);
                transform_px(u1, px, cfT4, s18 + 9);
                uint32_t* zh = reinterpret_cast<uint32_t*>(
                    smem + OFF_Z + (nn0 + px) * ZSTRIDE + zcol);
#pragma unroll
                for (int j = 0; j < 9; ++j) {
                    __half a  = __float2half_rn(s18[2 * j]);
                    __half c2 = __float2half_rn(s18[2 * j + 1]);
                    zh[j] = (uint32_t)__half_as_ushort(a) |
                            ((uint32_t)__half_as_ushort(c2) << 16);
                }
            }
        }
    }
    __syncthreads();   // z ready

    // ---- GEMM: K-split halves (18 k-steps of 16), warp tile 64n x 32m
    float acc[4][4][4];
#pragma unroll
    for (int i = 0; i < 4; ++i)
#pragma unroll
        for (int j = 0; j < 4; ++j)
#pragma unroll
            for (int q = 0; q < 4; ++q) acc[i][j][q] = 0.0f;

#pragma unroll 2
    for (int ks = ksp * 18; ks < ksp * 18 + 18; ++ks) {
        uint32_t aAddr = aBase + (uint32_t)ks * 32;
        uint32_t a[4][4];
#pragma unroll
        for (int nb = 0; nb < 4; ++nb)
            ldm_x4(a[nb], aAddr + (uint32_t)nb * (16 * ZSTRIDE));
        int ch = ks >> 2, ksi = ks & 3;
        const uint4* wp = wf0 + (uint32_t)((ch * 4 + ksi) * 2) * 32;
        uint4 b0 = __ldg(wp);
        uint4 b1 = __ldg(wp + 32);
#pragma unroll
        for (int nb = 0; nb < 4; ++nb) {
            mma16816(acc[nb][0], a[nb], b0.x, b0.y);
            mma16816(acc[nb][1], a[nb], b0.z, b0.w);
            mma16816(acc[nb][2], a[nb], b1.x, b1.y);
            mma16816(acc[nb][3], a[nb], b1.z, b1.w);
        }
    }
    __syncthreads();   // all z reads done; Z region -> epilogue buffer

    // ---- epilogue: ksp0 stores partials, ksp1 accumulates, then coalesced out
    float* ob = reinterpret_cast<float*>(smem + OFF_OB);
    const int mcb = mq * 32 + ((lid & 3) << 1);
    if (ksp == 0) {
#pragma unroll
        for (int nb = 0; nb < 4; ++nb) {
            int r0 = nb * 16 + (lid >> 2);
#pragma unroll
            for (int mb = 0; mb < 4; ++mb) {
                int mc = mcb + mb * 8;
                ob[r0 * 129 + mc]           = acc[nb][mb][0];
                ob[r0 * 129 + mc + 1]       = acc[nb][mb][1];
                ob[(r0 + 8) * 129 + mc]     = acc[nb][mb][2];
                ob[(r0 + 8) * 129 + mc + 1] = acc[nb][mb][3];
            }
        }
    }
    __syncthreads();
    if (ksp == 1) {
#pragma unroll
        for (int nb = 0; nb < 4; ++nb) {
            int r0 = nb * 16 + (lid >> 2);
#pragma unroll
            for (int mb = 0; mb < 4; ++mb) {
                int mc = mcb + mb * 8;
                ob[r0 * 129 + mc]           += acc[nb][mb][0];
                ob[r0 * 129 + mc + 1]       += acc[nb][mb][1];
                ob[(r0 + 8) * 129 + mc]     += acc[nb][mb][2];
                ob[(r0 + 8) * 129 + mc + 1] += acc[nb][mb][3];
            }
        }
    }
    __syncthreads();

    const long long obase0 = (((long long)b * 128) * 128 + h) * 128 + w0;
#pragma unroll
    for (int it = 0; it < 8; ++it) {
        int m = it * 16 + (t >> 4);
        int g = t & 15;
        float bv = __ldg(biasg + m);
        int n0s = 4 * g;
        float4 o;
        o.x = ob[(n0s + 0) * 129 + m] + bv;
        o.y = ob[(n0s + 1) * 129 + m] + bv;
        o.z = ob[(n0s + 2) * 129 + m] + bv;
        o.w = ob[(n0s + 3) * 129 + m] + bv;
        *reinterpret_cast<float4*>(outg + obase0 + ((long long)m << 14) + n0s) = o;
    }
}

extern "C" void kernel_launch(void* const* d_in, const int* in_sizes, int n_in,
                              void* d_out, int out_size) {
    const float *x = nullptr, *coef = nullptr, *w = nullptr, *bias = nullptr;
    for (int i = 0; i < n_in; ++i) {
        switch (in_sizes[i]) {
            case 8388608: x    = (const float*)d_in[i]; break;
            case 81:      coef = (const float*)d_in[i]; break;
            case 73728:   w    = (const float*)d_in[i]; break;
            case 128:     bias = (const float*)d_in[i]; break;
        }
    }
    prepack_w<<<36, 1024>>>(w);
    cudaFuncSetAttribute(sconv_mma_kernel,
                         cudaFuncAttributeMaxDynamicSharedMemorySize, SMEM_BYTES);
    dim3 grid(2, 128, 8);
    sconv_mma_kernel<<<grid, NTHREADS, SMEM_BYTES>>>(x, coef, bias, (float*)d_out);
}

// round 16
// speedup vs baseline: 1.6284x; 1.6284x over previous
#include <cuda_runtime.h>
#include <cuda_fp16.h>
#include <cstdint>

// Fused SConv via warp-level fp16 mma.sync GEMM.
// out[m=128, n] = sum_k W[m,k] * z[k,n], K=576, 64 pixels per CTA.
// R16: K-chunked z (two 288-k halves, 37.9KB buffer) -> 66KB smem ->
//      3 CTAs/SM. 32n x 32m warp tiles (2nt x 4mq), single-pass epilogue.

#define NTHREADS 256
#define ZSTRIDE 592          // 288*2 + 16 pad (ldmatrix conflict-free)
#define XR 72                // floats per x row (cols w0-4 .. w0+67)
#define XC 217               // floats per channel (3*72 + 1 pad)

#define OFF_Z   0            // 64 x 592 = 37888
#define OFF_XS  37888        // 32*217*4 = 27776
#define OFF_OB  0            // epilogue [64][129] f32 = 33024 (overlaps Z, after GEMM)
#define OFF_CF  65664        // cfT: 9 j x 8 q floats = 288B
#define SMEM_BYTES 66048

// W fragment buffer: [mq 4][ch 9][ks 4][p 2][lane 32] x uint4 (4 regs)
__device__ __align__(16) uint32_t g_Wfrag[4 * 9 * 4 * 2 * 32 * 4];

__device__ __forceinline__ uint32_t smem_u32(const void* p) {
    uint32_t a;
    asm("{ .reg .u64 t; cvta.to.shared.u64 t, %1; cvt.u32.u64 %0, t; }" : "=r"(a) : "l"(p));
    return a;
}
__device__ __forceinline__ void ldm_x4(uint32_t* r, uint32_t addr) {
    asm volatile("ldmatrix.sync.aligned.m8n8.x4.shared.b16 {%0,%1,%2,%3}, [%4];"
                 : "=r"(r[0]), "=r"(r[1]), "=r"(r[2]), "=r"(r[3]) : "r"(addr));
}
__device__ __forceinline__ void mma16816(float* d, const uint32_t* a,
                                         uint32_t b0, uint32_t b1) {
    asm volatile("mma.sync.aligned.m16n8k16.row.col.f32.f16.f16.f32 "
                 "{%0,%1,%2,%3}, {%4,%5,%6,%7}, {%8,%9}, {%0,%1,%2,%3};"
                 : "+f"(d[0]), "+f"(d[1]), "+f"(d[2]), "+f"(d[3])
                 : "r"(a[0]), "r"(a[1]), "r"(a[2]), "r"(a[3]), "r"(b0), "r"(b1));
}

// ---------------- W pre-pack into fragment order ----------------
__global__ void prepack_w(const float* __restrict__ wg) {
    int idx = blockIdx.x * blockDim.x + threadIdx.x;   // 36864
    if (idx >= 4 * 9 * 4 * 2 * 32 * 4) return;
    int q = idx & 3;  int r = idx >> 2;
    int l = r & 31;   r >>= 5;
    int p = r & 1;    r >>= 1;
    int ks = r & 3;   r >>= 2;
    int ch = r % 9;
    int mq = r / 9;
    int m = mq * 32 + p * 16 + ((q >> 1) << 3) + (l >> 2);
    int k = ch * 64 + ks * 16 + ((q & 1) << 3) + ((l & 3) << 1);
    __half h0 = __float2half_rn(wg[m * 576 + k]);
    __half h1 = __float2half_rn(wg[m * 576 + k + 1]);
    g_Wfrag[idx] = (uint32_t)__half_as_ushort(h0) |
                   ((uint32_t)__half_as_ushort(h1) << 16);
}

#define SORT8(yv)                                                                   \
{                                                                                   \
    /* Batcher odd-even mergesort, 19 comparators, ascending */                     \
    auto _cs = [&](int a, int bb) {                                                 \
        float _l = fminf(yv[a], yv[bb]); float _h = fmaxf(yv[a], yv[bb]);           \
        yv[a] = _l; yv[bb] = _h; };                                                 \
    _cs(0,1); _cs(2,3); _cs(4,5); _cs(6,7);                                         \
    _cs(0,2); _cs(1,3); _cs(4,6); _cs(5,7);                                         \
    _cs(1,2); _cs(5,6);                                                             \
    _cs(0,4); _cs(1,5); _cs(2,6); _cs(3,7);                                         \
    _cs(2,4); _cs(3,5);                                                             \
    _cs(1,2); _cs(3,4); _cs(5,6);                                                   \
}

// ---------------- main fused kernel ----------------
__global__ __launch_bounds__(NTHREADS, 3)
void sconv_mma_kernel(const float* __restrict__ xg,
                      const float* __restrict__ coefg,
                      const float* __restrict__ biasg,
                      float* __restrict__ outg) {
    extern __shared__ __align__(1024) unsigned char smem[];
    const uint32_t sb = smem_u32(smem);
    const int t   = threadIdx.x;
    const int wid = t >> 5;
    const int lid = t & 31;
    const int b   = blockIdx.z;
    const int h   = blockIdx.y;
    const int w0  = blockIdx.x * 64;

    float* xs = reinterpret_cast<float*>(smem + OFF_XS);
    float* cfT = reinterpret_cast<float*>(smem + OFF_CF);
    const float4* cfT4 = reinterpret_cast<const float4*>(smem + OFF_CF);

    if (t < 72) {
        int j = t >> 3, q = t & 7;
        int ri = q + (q >= 4 ? 1 : 0);
        cfT[j * 8 + q] = coefg[ri * 9 + j];
    }

    // warp roles: nt = wid&1 (32-px half), mq = wid>>1 (32-m quarter)
    const int nt = wid & 1;
    const int mq = wid >> 1;
    const int n0 = nt * 32;

    // A (z) ldmatrix x4 addressing: 16n x 16k tiles (nb adds nb*16*ZSTRIDE)
    const int rA   = lid & 7;
    const int matA = lid >> 3;
    const uint32_t aBase = sb + OFF_Z +
        (uint32_t)(n0 + rA + ((matA & 1) << 3)) * ZSTRIDE + (((matA >> 1) << 3) << 1);

    const uint4* wf0 = reinterpret_cast<const uint4*>(g_Wfrag) +
                       (uint32_t)mq * (9 * 4 * 2 * 32) + lid;

    // transform lane roles: cp = ch-pair, q4 = pixel quad
    const int cp  = t & 15;
    const int q4  = t >> 4;           // 0..15
    const int nn0 = q4 * 4;

    float acc[2][4][4];
#pragma unroll
    for (int i = 0; i < 2; ++i)
#pragma unroll
        for (int j = 0; j < 4; ++j)
#pragma unroll
            for (int q = 0; q < 4; ++q) acc[i][j][q] = 0.0f;

    // ---- two K halves: build z (288 k) then GEMM it, accumulating
    for (int cc = 0; cc < 2; ++cc) {
        __syncthreads();   // prev GEMM z-reads + transform xs-reads done

        // stage x: ch = t>>3, lane8 = t&7; 18 float4 x 3 rows per channel
        {
            const float* xb = xg + (((long long)b * 64 + cc * 32) << 14);
            int c    = t >> 3;
            int l8   = t & 7;
            const float* xc = xb + (c << 14);
            float* xd = xs + c * XC;
#pragma unroll
            for (int j0 = 0; j0 < 7; ++j0) {
                int j = l8 + j0 * 8;
                if (j < 54) {
                    int r = j / 18, v = j % 18;
                    int gr = h + r - 1;
                    int gcb = w0 - 4 + 4 * v;
                    float4 val = make_float4(0.f, 0.f, 0.f, 0.f);
                    if ((unsigned)gr < 128u && gcb >= 0 && gcb + 3 < 128)
                        val = *reinterpret_cast<const float4*>(xc + (gr << 7) + gcb);
                    float* d = xd + r * XR + 4 * v;
                    d[0] = val.x; d[1] = val.y; d[2] = val.z; d[3] = val.w;
                }
            }
        }
        __syncthreads();

        // transform: thread = (local ch pair 2cp,2cp+1) x (pixel quad)
        // channel A window in registers; channel B streamed from smem.
        {
            const float* xr0 = xs + (2 * cp) * XC;
            const float* xr1 = xr0 + XC;
            float u0[18];
#pragma unroll
            for (int r = 0; r < 3; ++r)
#pragma unroll
                for (int c2 = 0; c2 < 6; ++c2)
                    u0[r * 6 + c2] = xr0[r * XR + nn0 + 3 + c2];

#pragma unroll
            for (int px = 0; px < 4; ++px) {
                float yA[8] = {0, 0, 0, 0, 0, 0, 0, 0};
                float yB[8] = {0, 0, 0, 0, 0, 0, 0, 0};
                float cB4 = 0.0f;
#pragma unroll
                for (int j = 0; j < 9; ++j) {
                    int r = j / 3, c2 = j % 3;
                    float vA = u0[r * 6 + px + c2];
                    float vB = xr1[r * XR + nn0 + 3 + px + c2];
                    if (j == 4) cB4 = vB;
                    float4 cA = cfT4[j * 2];
                    float4 cBv = cfT4[j * 2 + 1];
                    yA[0] = fmaf(cA.x, vA, yA[0]); yA[1] = fmaf(cA.y, vA, yA[1]);
                    yA[2] = fmaf(cA.z, vA, yA[2]); yA[3] = fmaf(cA.w, vA, yA[3]);
                    yA[4] = fmaf(cBv.x, vA, yA[4]); yA[5] = fmaf(cBv.y, vA, yA[5]);
                    yA[6] = fmaf(cBv.z, vA, yA[6]); yA[7] = fmaf(cBv.w, vA, yA[7]);
                    yB[0] = fmaf(cA.x, vB, yB[0]); yB[1] = fmaf(cA.y, vB, yB[1]);
                    yB[2] = fmaf(cA.z, vB, yB[2]); yB[3] = fmaf(cA.w, vB, yB[3]);
                    yB[4] = fmaf(cBv.x, vB, yB[4]); yB[5] = fmaf(cBv.y, vB, yB[5]);
                    yB[6] = fmaf(cBv.z, vB, yB[6]); yB[7] = fmaf(cBv.w, vB, yB[7]);
                }
                SORT8(yA);
                SORT8(yB);
                float cA4 = u0[6 + px + 1];
                float s18[18] = { yA[0], yA[1], yA[2], yA[3], cA4,
                                  yA[4], yA[5], yA[6], yA[7],
                                  yB[0], yB[1], yB[2], yB[3], cB4,
                                  yB[4], yB[5], yB[6], yB[7] };
                uint32_t* zh = reinterpret_cast<uint32_t*>(
                    smem + OFF_Z + (nn0 + px) * ZSTRIDE + cp * 36);
#pragma unroll
                for (int j = 0; j < 9; ++j) {
                    __half a  = __float2half_rn(s18[2 * j]);
                    __half c2 = __float2half_rn(s18[2 * j + 1]);
                    zh[j] = (uint32_t)__half_as_ushort(a) |
                            ((uint32_t)__half_as_ushort(c2) << 16);
                }
            }
        }
        __syncthreads();   // z half ready

        // ---- GEMM over this K half: 18 k-steps of 16
#pragma unroll 2
        for (int ks = 0; ks < 18; ++ks) {
            int gks = cc * 18 + ks;
            uint32_t aAddr = aBase + (uint32_t)ks * 32;
            uint32_t a0[4], a1[4];
            ldm_x4(a0, aAddr);
            ldm_x4(a1, aAddr + 16 * ZSTRIDE);
            int ch = gks >> 2, ksi = gks & 3;
            const uint4* wp = wf0 + (uint32_t)((ch * 4 + ksi) * 2) * 32;
            uint4 b0 = __ldg(wp);
            uint4 b1 = __ldg(wp + 32);
            mma16816(acc[0][0], a0, b0.x, b0.y);
            mma16816(acc[0][1], a0, b0.z, b0.w);
            mma16816(acc[1][0], a1, b0.x, b0.y);
            mma16816(acc[1][1], a1, b0.z, b0.w);
            mma16816(acc[0][2], a0, b1.x, b1.y);
            mma16816(acc[0][3], a0, b1.z, b1.w);
            mma16816(acc[1][2], a1, b1.x, b1.y);
            mma16816(acc[1][3], a1, b1.z, b1.w);
        }
    }
    __syncthreads();   // all z reads done; Z region -> epilogue buffer

    // ---- epilogue: fragments -> smem [n 64][129] f32 -> coalesced float4 stores
    float* ob = reinterpret_cast<float*>(smem + OFF_OB);
    {
        int mc0 = mq * 32 + ((lid & 3) << 1);
#pragma unroll
        for (int nb = 0; nb < 2; ++nb) {
            int r0 = n0 + nb * 16 + (lid >> 2);
#pragma unroll
            for (int mb = 0; mb < 4; ++mb) {
                int mc = mc0 + mb * 8;
                ob[r0 * 129 + mc]           = acc[nb][mb][0];
                ob[r0 * 129 + mc + 1]       = acc[nb][mb][1];
                ob[(r0 + 8) * 129 + mc]     = acc[nb][mb][2];
                ob[(r0 + 8) * 129 + mc + 1] = acc[nb][mb][3];
            }
        }
    }
    __syncthreads();

    const long long obase0 = (((long long)b * 128) * 128 + h) * 128 + w0;
#pragma unroll
    for (int it = 0; it < 8; ++it) {
        int m = it * 16 + (t >> 4);
        int g = t & 15;
        float bv = __ldg(biasg + m);
        int n0s = 4 * g;
        float4 o;
        o.x = ob[(n0s + 0) * 129 + m] + bv;
        o.y = ob[(n0s + 1) * 129 + m] + bv;
        o.z = ob[(n0s + 2) * 129 + m] + bv;
        o.w = ob[(n0s + 3) * 129 + m] + bv;
        *reinterpret_cast<float4*>(outg + obase0 + ((long long)m << 14) + n0s) = o;
    }
}

extern "C" void kernel_launch(void* const* d_in, const int* in_sizes, int n_in,
                              void* d_out, int out_size) {
    const float *x = nullptr, *coef = nullptr, *w = nullptr, *bias = nullptr;
    for (int i = 0; i < n_in; ++i) {
        switch (in_sizes[i]) {
            case 8388608: x    = (const float*)d_in[i]; break;
            case 81:      coef = (const float*)d_in[i]; break;
            case 73728:   w    = (const float*)d_in[i]; break;
            case 128:     bias = (const float*)d_in[i]; break;
        }
    }
    prepack_w<<<36, 1024>>>(w);
    cudaFuncSetAttribute(sconv_mma_kernel,
                         cudaFuncAttributeMaxDynamicSharedMemorySize, SMEM_BYTES);
    dim3 grid(2, 128, 8);
    sconv_mma_kernel<<<grid, NTHREADS, SMEM_BYTES>>>(x, coef, bias, (float*)d_out);
}